// round 17
// baseline (speedup 1.0000x reference)
#include <cuda_runtime.h>

#define T_DIM 4096
#define B_DIM 64
#define F_DIM 64
#define CS    64               // output chunk size
#define WU    80               // warm-up steps (empirical optimum)
#define TS_MIN 128             // below this, transient seed error not decayed -> run exact
#define NC    (T_DIM / CS)     // 64 chunks
#define LAG   25
#define NTOT  ((size_t)B_DIM * T_DIM * F_DIM)   // 16777216

#define ALPHA (2.0f / 26.0f)
#define OM    (24.0f / 26.0f)

// Seed scratch: (e, el) per (chunk, b, f2). 64*64*32 float2 = 1MB each.
__device__ float2 g_seedE[NC * B_DIM * 32];
__device__ float2 g_seedL[NC * B_DIM * 32];

__device__ __forceinline__ void estep(float2& e, const float2 xv, int t) {
    // e = (alpha * x_t + om * e_prev) / max(1 - om^(t+1), 1e-10)
    e.x = fmaf(OM, e.x, ALPHA * xv.x);
    e.y = fmaf(OM, e.y, ALPHA * xv.y);
    if (t < 192) {             // for t >= 166, om^(t+1) underflows below fp32 ulp of 1
        float w  = 1.0f - __powf(OM, (float)(t + 1));
        float iw = 1.0f / fmaxf(w, 1e-10f);
        e.x *= iw; e.y *= iw;
    }
}

__device__ __forceinline__ void writeout(float* __restrict__ out, size_t pos,
                                         const float2 e, const float2 lag) {
    float2 s;
    s.x = e.x - lag.x; s.y = e.y - lag.y;
    float2 ab, bl, bt;
    ab.x = (s.x >  15.0f) ? 1.0f : 0.0f;
    ab.y = (s.y >  15.0f) ? 1.0f : 0.0f;
    bl.x = (s.x < -15.0f) ? 1.0f : 0.0f;
    bl.y = (s.y < -15.0f) ? 1.0f : 0.0f;
    bt.x = 1.0f - ab.x - bl.x;
    bt.y = 1.0f - ab.y - bl.y;
    __stcs((float2*)(out +            pos), e);
    __stcs((float2*)(out + NTOT     + pos), s);
    __stcs((float2*)(out + 2 * NTOT + pos), ab);
    __stcs((float2*)(out + 3 * NTOT + pos), bl);
    __stcs((float2*)(out + 4 * NTOT + pos), bt);
}

// ---------------- Kernel S: compute warm-up seeds (no output stores) ----------------
__global__ void __launch_bounds__(128, 7)
ema_seed_kernel(const float* __restrict__ x) {
    int gtid = blockIdx.x * blockDim.x + threadIdx.x;
    int f2 = gtid & 31;
    int b  = (gtid >> 5) & 63;
    int c  = gtid >> 11;

    if (c == 0) return;                 // chunk 0 needs no seed (exact prefix in kernel O)

    const float2* xb = (const float2*)(x + (size_t)b * T_DIM * F_DIM) + f2;

    int t0 = c * CS;
    int ts = t0 - WU;
    // Adjusted-EMA transient is explosive; seeds inside it are wrong -> run exact.
    if (ts < TS_MIN) ts = 0;

    float2 e = xb[(size_t)ts * 32];

    int t = ts + 1;
    int tsnap = t0 - 1 - LAG;

    // phase A: single-chain warm-up to tsnap, batches of 8
    #pragma unroll 1
    for (; t + 8 <= tsnap + 1; t += 8) {
        float2 xt[8];
        #pragma unroll
        for (int u = 0; u < 8; ++u) xt[u] = xb[(size_t)(t + u) * 32];
        #pragma unroll
        for (int u = 0; u < 8; ++u) estep(e, xt[u], t + u);
    }
    #pragma unroll 1
    for (; t <= tsnap; ++t) estep(e, xb[(size_t)t * 32], t);

    float2 el = e;                      // el = ema[t0-1-LAG]

    // phase B: advance e alone the last LAG=25 steps (13 + 12)
    {
        float2 xt[13];
        #pragma unroll
        for (int u = 0; u < 13; ++u) xt[u] = xb[(size_t)(t + u) * 32];
        #pragma unroll
        for (int u = 0; u < 13; ++u) estep(e, xt[u], t + u);
        t += 13;
        float2 x2[12];
        #pragma unroll
        for (int u = 0; u < 12; ++u) x2[u] = xb[(size_t)(t + u) * 32];
        #pragma unroll
        for (int u = 0; u < 12; ++u) estep(e, x2[u], t + u);
        t += 12;                        // t == t0
    }

    int idx = (c * B_DIM + b) * 32 + f2;
    g_seedE[idx] = e;                   // ema[t0-1]
    g_seedL[idx] = el;                  // ema[t0-1-LAG]
}

// ---------------- Kernel O: pure streaming output ----------------
__global__ void __launch_bounds__(128, 7)
ema_out_kernel(const float* __restrict__ x, float* __restrict__ out) {
    int gtid = blockIdx.x * blockDim.x + threadIdx.x;
    int f2 = gtid & 31;
    int b  = (gtid >> 5) & 63;
    int c  = gtid >> 11;

    const float2* xb = (const float2*)(x + (size_t)b * T_DIM * F_DIM) + f2;
    size_t obase = (size_t)b * T_DIM * F_DIM + (size_t)f2 * 2;

    if (c == 0) {
        // exact prefix: t < LAG has lagged = 0; el chain starts stepping at tl = 1
        float2 e  = xb[0];
        float2 el = e;
        float2 z  = make_float2(0.f, 0.f);
        writeout(out, obase, e, z);
        for (int t = 1; t < LAG; ++t) {
            estep(e, xb[(size_t)t * 32], t);
            writeout(out, obase + (size_t)t * F_DIM, e, z);
        }
        for (int t = LAG; t < CS; ++t) {
            estep(e, xb[(size_t)t * 32], t);
            if (t > LAG)                // first el step at tl=1 (el seed IS ema[0])
                estep(el, xb[(size_t)(t - LAG) * 32], t - LAG);
            writeout(out, obase + (size_t)t * F_DIM, e, el);
        }
        return;
    }

    int idx = (c * B_DIM + b) * 32 + f2;
    float2 e  = g_seedE[idx];           // ema[t0-1]
    float2 el = g_seedL[idx];           // ema[t0-1-LAG]

    int t0 = c * CS;
    int te = t0 + CS;
    int t  = t0;

    // output: compute 8 steps, store grouped by stream (2KB bursts per stream per warp)
    #pragma unroll 1
    for (; t < te; t += 8) {
        float2 xt[8], xl[8];
        #pragma unroll
        for (int u = 0; u < 8; ++u) xt[u] = xb[(size_t)(t + u) * 32];
        #pragma unroll
        for (int u = 0; u < 8; ++u) xl[u] = xb[(size_t)(t + u - LAG) * 32];

        float2 eo[8], so[8];
        #pragma unroll
        for (int u = 0; u < 8; ++u) {
            estep(e,  xt[u], t + u);
            estep(el, xl[u], t + u - LAG);
            eo[u] = e;
            so[u] = make_float2(e.x - el.x, e.y - el.y);
        }

        size_t p = obase + (size_t)t * F_DIM;
        #pragma unroll
        for (int u = 0; u < 8; ++u)
            __stcs((float2*)(out + p + (size_t)u * F_DIM), eo[u]);
        #pragma unroll
        for (int u = 0; u < 8; ++u)
            __stcs((float2*)(out + NTOT + p + (size_t)u * F_DIM), so[u]);
        #pragma unroll
        for (int u = 0; u < 8; ++u) {
            float2 ab;
            ab.x = (so[u].x > 15.0f) ? 1.0f : 0.0f;
            ab.y = (so[u].y > 15.0f) ? 1.0f : 0.0f;
            __stcs((float2*)(out + 2 * NTOT + p + (size_t)u * F_DIM), ab);
        }
        #pragma unroll
        for (int u = 0; u < 8; ++u) {
            float2 bl;
            bl.x = (so[u].x < -15.0f) ? 1.0f : 0.0f;
            bl.y = (so[u].y < -15.0f) ? 1.0f : 0.0f;
            __stcs((float2*)(out + 3 * NTOT + p + (size_t)u * F_DIM), bl);
        }
        #pragma unroll
        for (int u = 0; u < 8; ++u) {
            float2 bt;
            bt.x = (so[u].x >= -15.0f && so[u].x <= 15.0f) ? 1.0f : 0.0f;
            bt.y = (so[u].y >= -15.0f && so[u].y <= 15.0f) ? 1.0f : 0.0f;
            __stcs((float2*)(out + 4 * NTOT + p + (size_t)u * F_DIM), bt);
        }
    }
}

extern "C" void kernel_launch(void* const* d_in, const int* in_sizes, int n_in,
                              void* d_out, int out_size) {
    const float* x = (const float*)d_in[0];
    float* out = (float*)d_out;
    int total = 32 * B_DIM * NC;        // 131072 threads
    ema_seed_kernel<<<total / 128, 128>>>(x);
    ema_out_kernel<<<total / 128, 128>>>(x, out);
}